// round 1
// baseline (speedup 1.0000x reference)
#include <cuda_runtime.h>

// Problem constants
#define BATCH   256
#define TSEQ    2048
#define SOBS    39
#define AACT    4
#define DIM     43          // S + A
#define HID     256
#define EPS     1e-5f

// Tiling
#define ROWS    32          // rows per block (divides TSEQ)
#define THREADS 256         // 8 warps; warp w owns rows w*4..w*4+3, lane owns cols lane*8..+7
#define KC      16          // W2 k-chunk
#define NCHUNK  (HID / KC)  // 16
#define NROWBLK (TSEQ / ROWS)        // 64 blocks per batch segment
#define NBLOCKS (BATCH * NROWBLK)    // 16384

// Deterministic scratch (no atomics anywhere)
__device__ float g_partials[NBLOCKS];

struct Smem {
    float W1s[DIM][HID];       // 44032 B
    float xs[ROWS][DIM + 1];   // 5632 B (pad to 44)
    float h1s[ROWS][HID];      // 32768 B
    float W2s[KC][HID];        // 16384 B
    float b1s[HID], g1s[HID], be1s[HID];
    float b2s[HID], g2s[HID], be2s[HID];
    float W3s[HID];            // 7*1024 B
    float bsum[8];
};                              // ~106 KB -> 2 blocks/SM

__device__ __forceinline__ float warp_sum(float v) {
    #pragma unroll
    for (int off = 16; off; off >>= 1)
        v += __shfl_xor_sync(0xffffffffu, v, off);
    return v;
}

__global__ __launch_bounds__(THREADS, 2)
void fused_mlp_kernel(const float* __restrict__ obs, const float* __restrict__ act,
                      const float* __restrict__ W1,  const float* __restrict__ b1,
                      const float* __restrict__ g1,  const float* __restrict__ be1,
                      const float* __restrict__ W2,  const float* __restrict__ b2,
                      const float* __restrict__ g2,  const float* __restrict__ be2,
                      const float* __restrict__ W3,  const float* __restrict__ b3)
{
    extern __shared__ char smraw[];
    Smem& s = *reinterpret_cast<Smem*>(smraw);

    const int tid  = threadIdx.x;
    const int warp = tid >> 5;
    const int lane = tid & 31;
    const long long row0 = (long long)blockIdx.x * ROWS;

    // ---- stage weights + vectors + x tile into SMEM ----
    {
        const float4* src = (const float4*)W1;
        float4* dst = (float4*)&s.W1s[0][0];
        #pragma unroll 4
        for (int i = tid; i < DIM * HID / 4; i += THREADS) dst[i] = src[i];
    }
    s.b1s[tid] = b1[tid];  s.g1s[tid] = g1[tid];  s.be1s[tid] = be1[tid];
    s.b2s[tid] = b2[tid];  s.g2s[tid] = g2[tid];  s.be2s[tid] = be2[tid];
    s.W3s[tid] = W3[tid];

    for (int idx = tid; idx < ROWS * DIM; idx += THREADS) {
        int r = idx / DIM, d = idx - r * DIM;
        long long grow = row0 + r;
        float v = (d < SOBS) ? obs[grow * SOBS + d]
                             : act[grow * AACT + (d - SOBS)];
        s.xs[r][d] = v;
    }
    __syncthreads();

    const int rbase = warp * 4;
    const int cbase = lane * 8;

    // ---- GEMM1: h1 = x @ W1 ----
    float acc[4][8];
    #pragma unroll
    for (int i = 0; i < 4; i++)
        #pragma unroll
        for (int j = 0; j < 8; j++) acc[i][j] = 0.f;

    #pragma unroll 4
    for (int d = 0; d < DIM; ++d) {
        float a0 = s.xs[rbase + 0][d];
        float a1 = s.xs[rbase + 1][d];
        float a2 = s.xs[rbase + 2][d];
        float a3 = s.xs[rbase + 3][d];
        float4 w0 = *(const float4*)&s.W1s[d][cbase];
        float4 w1 = *(const float4*)&s.W1s[d][cbase + 4];
        float w[8] = {w0.x, w0.y, w0.z, w0.w, w1.x, w1.y, w1.z, w1.w};
        #pragma unroll
        for (int j = 0; j < 8; j++) {
            acc[0][j] = fmaf(a0, w[j], acc[0][j]);
            acc[1][j] = fmaf(a1, w[j], acc[1][j]);
            acc[2][j] = fmaf(a2, w[j], acc[2][j]);
            acc[3][j] = fmaf(a3, w[j], acc[3][j]);
        }
    }

    // ---- bias + LayerNorm1 + ReLU (rows live entirely in one warp) ----
    #pragma unroll
    for (int i = 0; i < 4; i++) {
        float sum = 0.f, sq = 0.f;
        #pragma unroll
        for (int j = 0; j < 8; j++) {
            float v = acc[i][j] + s.b1s[cbase + j];
            acc[i][j] = v;
            sum += v;
            sq  = fmaf(v, v, sq);
        }
        sum = warp_sum(sum);
        sq  = warp_sum(sq);
        float mu  = sum * (1.f / HID);
        float var = sq * (1.f / HID) - mu * mu;
        float z   = var + EPS;
        float rs  = rsqrtf(z);
        rs = rs * (1.5f - 0.5f * z * rs * rs);   // Newton refine
        #pragma unroll
        for (int j = 0; j < 8; j++) {
            float v = (acc[i][j] - mu) * rs * s.g1s[cbase + j] + s.be1s[cbase + j];
            acc[i][j] = fmaxf(v, 0.f);
        }
    }

    // write h1 tile (row-major, coalesced STS.128, broadcast-friendly reads)
    #pragma unroll
    for (int i = 0; i < 4; i++) {
        *(float4*)&s.h1s[rbase + i][cbase]     = make_float4(acc[i][0], acc[i][1], acc[i][2], acc[i][3]);
        *(float4*)&s.h1s[rbase + i][cbase + 4] = make_float4(acc[i][4], acc[i][5], acc[i][6], acc[i][7]);
    }

    // ---- GEMM2: h2 = h1 @ W2, streaming W2 in KC-row chunks w/ register prefetch ----
    float acc2[4][8];
    #pragma unroll
    for (int i = 0; i < 4; i++)
        #pragma unroll
        for (int j = 0; j < 8; j++) acc2[i][j] = 0.f;

    float4 pre[4];
    {
        const float4* w2g = (const float4*)W2;
        #pragma unroll
        for (int q = 0; q < 4; q++) pre[q] = w2g[q * 256 + tid];
    }

    for (int c = 0; c < NCHUNK; ++c) {
        __syncthreads();                 // W2s free (+ h1s visible on first iter path)
        float4* w2s4 = (float4*)&s.W2s[0][0];
        #pragma unroll
        for (int q = 0; q < 4; q++) w2s4[q * 256 + tid] = pre[q];
        if (c + 1 < NCHUNK) {
            const float4* w2g = (const float4*)W2;
            #pragma unroll
            for (int q = 0; q < 4; q++) pre[q] = w2g[(c + 1) * 1024 + q * 256 + tid];
        }
        __syncthreads();

        const int kb = c * KC;
        #pragma unroll
        for (int kk = 0; kk < KC; ++kk) {
            float a0 = s.h1s[rbase + 0][kb + kk];
            float a1 = s.h1s[rbase + 1][kb + kk];
            float a2 = s.h1s[rbase + 2][kb + kk];
            float a3 = s.h1s[rbase + 3][kb + kk];
            float4 w0 = *(const float4*)&s.W2s[kk][cbase];
            float4 w1 = *(const float4*)&s.W2s[kk][cbase + 4];
            float w[8] = {w0.x, w0.y, w0.z, w0.w, w1.x, w1.y, w1.z, w1.w};
            #pragma unroll
            for (int j = 0; j < 8; j++) {
                acc2[0][j] = fmaf(a0, w[j], acc2[0][j]);
                acc2[1][j] = fmaf(a1, w[j], acc2[1][j]);
                acc2[2][j] = fmaf(a2, w[j], acc2[2][j]);
                acc2[3][j] = fmaf(a3, w[j], acc2[3][j]);
            }
        }
    }

    // ---- bias + LayerNorm2 + ReLU + Linear(H->1), all in registers ----
    float rtot = 0.f;
    #pragma unroll
    for (int i = 0; i < 4; i++) {
        float sum = 0.f, sq = 0.f;
        #pragma unroll
        for (int j = 0; j < 8; j++) {
            float v = acc2[i][j] + s.b2s[cbase + j];
            acc2[i][j] = v;
            sum += v;
            sq  = fmaf(v, v, sq);
        }
        sum = warp_sum(sum);
        sq  = warp_sum(sq);
        float mu  = sum * (1.f / HID);
        float var = sq * (1.f / HID) - mu * mu;
        float z   = var + EPS;
        float rs  = rsqrtf(z);
        rs = rs * (1.5f - 0.5f * z * rs * rs);
        float rp = 0.f;
        #pragma unroll
        for (int j = 0; j < 8; j++) {
            float v = (acc2[i][j] - mu) * rs * s.g2s[cbase + j] + s.be2s[cbase + j];
            v = fmaxf(v, 0.f);
            rp = fmaf(v, s.W3s[cbase + j], rp);
        }
        rtot += rp;
    }
    rtot = warp_sum(rtot);
    if (lane == 0) s.bsum[warp] = rtot;
    __syncthreads();
    if (tid == 0) {
        float t = 0.f;
        #pragma unroll
        for (int w = 0; w < 8; w++) t += s.bsum[w];
        t += (float)ROWS * b3[0];          // +b3 per row
        g_partials[blockIdx.x] = t;
    }
}

// Deterministic final reduction: out[b] = sum of 64 per-block partials
__global__ void reduce_kernel(float* __restrict__ out)
{
    const int b = blockIdx.x;
    float v = g_partials[b * NROWBLK + threadIdx.x];   // 64 threads
    #pragma unroll
    for (int off = 16; off; off >>= 1)
        v += __shfl_xor_sync(0xffffffffu, v, off);
    __shared__ float tmp[2];
    if ((threadIdx.x & 31) == 0) tmp[threadIdx.x >> 5] = v;
    __syncthreads();
    if (threadIdx.x == 0) out[b] = tmp[0] + tmp[1];
}

extern "C" void kernel_launch(void* const* d_in, const int* in_sizes, int n_in,
                              void* d_out, int out_size)
{
    const float* obs = (const float*)d_in[0];
    const float* act = (const float*)d_in[1];
    const float* W1  = (const float*)d_in[2];
    const float* b1  = (const float*)d_in[3];
    const float* g1  = (const float*)d_in[4];
    const float* be1 = (const float*)d_in[5];
    const float* W2  = (const float*)d_in[6];
    const float* b2  = (const float*)d_in[7];
    const float* g2  = (const float*)d_in[8];
    const float* be2 = (const float*)d_in[9];
    const float* W3  = (const float*)d_in[10];
    const float* b3  = (const float*)d_in[11];

    cudaFuncSetAttribute(fused_mlp_kernel,
                         cudaFuncAttributeMaxDynamicSharedMemorySize,
                         (int)sizeof(Smem));

    fused_mlp_kernel<<<NBLOCKS, THREADS, sizeof(Smem)>>>(
        obs, act, W1, b1, g1, be1, W2, b2, g2, be2, W3, b3);

    reduce_kernel<<<BATCH, NROWBLK>>>((float*)d_out);
}

// round 2
// speedup vs baseline: 1.3726x; 1.3726x over previous
#include <cuda_runtime.h>

// Problem constants
#define BATCH   256
#define TSEQ    2048
#define SOBS    39
#define AACT    4
#define DIM     43          // S + A
#define HID     256
#define EPS     1e-5f

// Tiling
#define ROWS    64          // rows per block (divides TSEQ)
#define THREADS 256         // 8 warps; warp w owns rows w*8..w*8+7, lane owns cols lane*8..+7
#define RPW     8           // rows per warp
#define KC      16          // W2 k-chunk
#define NCHUNK  (HID / KC)  // 16
#define NROWBLK (TSEQ / ROWS)        // 32 blocks per batch segment
#define NBLOCKS (BATCH * NROWBLK)    // 8192

// Deterministic scratch (no atomics anywhere)
__device__ float g_partials[NBLOCKS];

typedef unsigned long long ull;

// ---- packed f32x2 helpers (FFMA2 path, ptxas never emits this from C++) ----
__device__ __forceinline__ ull pack2(float lo, float hi) {
    ull r; asm("mov.b64 %0,{%1,%2};" : "=l"(r) : "f"(lo), "f"(hi)); return r;
}
__device__ __forceinline__ void fma2(ull& d, ull a, ull b) {
    asm("fma.rn.f32x2 %0,%1,%2,%0;" : "+l"(d) : "l"(a), "l"(b));
}
__device__ __forceinline__ float2 unpack2(ull v) {
    float2 f; asm("mov.b64 {%0,%1},%2;" : "=f"(f.x), "=f"(f.y) : "l"(v)); return f;
}

struct Smem {
    float W1s[DIM][HID];       // 44032 B
    float xs[ROWS][DIM + 1];   // 11264 B (pad to 44)
    float h1s[ROWS][HID];      // 65536 B
    float W2s[KC][HID];        // 16384 B
    float b1s[HID], g1s[HID], be1s[HID];
    float b2s[HID], g2s[HID], be2s[HID];
    float W3s[HID];            // 7168 B
    float bsum[8];
};                              // ~141 KB -> 1 block/SM

__device__ __forceinline__ float warp_sum(float v) {
    #pragma unroll
    for (int off = 16; off; off >>= 1)
        v += __shfl_xor_sync(0xffffffffu, v, off);
    return v;
}

__global__ __launch_bounds__(THREADS, 1)
void fused_mlp_kernel(const float* __restrict__ obs, const float* __restrict__ act,
                      const float* __restrict__ W1,  const float* __restrict__ b1,
                      const float* __restrict__ g1,  const float* __restrict__ be1,
                      const float* __restrict__ W2,  const float* __restrict__ b2,
                      const float* __restrict__ g2,  const float* __restrict__ be2,
                      const float* __restrict__ W3,  const float* __restrict__ b3)
{
    extern __shared__ char smraw[];
    Smem& s = *reinterpret_cast<Smem*>(smraw);

    const int tid  = threadIdx.x;
    const int warp = tid >> 5;
    const int lane = tid & 31;
    const long long row0 = (long long)blockIdx.x * ROWS;

    // ---- prefetch W2 chunk 0 into registers (overlaps with GEMM1) ----
    float4 pre[4];
    {
        const float4* w2g = (const float4*)W2;
        #pragma unroll
        for (int q = 0; q < 4; q++) pre[q] = w2g[q * 256 + tid];
    }

    // ---- stage W1 + vectors + x tile into SMEM ----
    {
        const float4* src = (const float4*)W1;
        float4* dst = (float4*)&s.W1s[0][0];
        #pragma unroll 4
        for (int i = tid; i < DIM * HID / 4; i += THREADS) dst[i] = src[i];
    }
    s.b1s[tid] = b1[tid];  s.g1s[tid] = g1[tid];  s.be1s[tid] = be1[tid];
    s.b2s[tid] = b2[tid];  s.g2s[tid] = g2[tid];  s.be2s[tid] = be2[tid];
    s.W3s[tid] = W3[tid];

    for (int idx = tid; idx < ROWS * DIM; idx += THREADS) {
        int r = idx / DIM, d = idx - r * DIM;
        long long grow = row0 + r;
        float v = (d < SOBS) ? obs[grow * SOBS + d]
                             : act[grow * AACT + (d - SOBS)];
        s.xs[r][d] = v;
    }
    __syncthreads();

    const int rbase = warp * RPW;
    const int cbase = lane * 8;

    // ---- GEMM1: h1 = x @ W1 (packed f32x2 accumulators) ----
    ull acc[RPW][4];
    #pragma unroll
    for (int i = 0; i < RPW; i++)
        #pragma unroll
        for (int j = 0; j < 4; j++) acc[i][j] = 0ull;

    #pragma unroll 1
    for (int d = 0; d < DIM; ++d) {
        float4 w0 = *(const float4*)&s.W1s[d][cbase];
        float4 w1 = *(const float4*)&s.W1s[d][cbase + 4];
        ull wp0 = pack2(w0.x, w0.y), wp1 = pack2(w0.z, w0.w);
        ull wp2 = pack2(w1.x, w1.y), wp3 = pack2(w1.z, w1.w);
        #pragma unroll
        for (int i = 0; i < RPW; i++) {
            float a = s.xs[rbase + i][d];
            ull ap = pack2(a, a);
            fma2(acc[i][0], ap, wp0);
            fma2(acc[i][1], ap, wp1);
            fma2(acc[i][2], ap, wp2);
            fma2(acc[i][3], ap, wp3);
        }
    }

    // ---- bias + LayerNorm1 + ReLU, write h1 tile ----
    #pragma unroll
    for (int i = 0; i < RPW; i++) {
        float2 v[4];
        float sum = 0.f, sq = 0.f;
        #pragma unroll
        for (int j = 0; j < 4; j++) {
            v[j] = unpack2(acc[i][j]);
            v[j].x += s.b1s[cbase + 2 * j];
            v[j].y += s.b1s[cbase + 2 * j + 1];
            sum += v[j].x + v[j].y;
            sq = fmaf(v[j].x, v[j].x, sq);
            sq = fmaf(v[j].y, v[j].y, sq);
        }
        sum = warp_sum(sum);
        sq  = warp_sum(sq);
        float mu  = sum * (1.f / HID);
        float var = sq * (1.f / HID) - mu * mu;
        float z   = var + EPS;
        float rs  = rsqrtf(z);
        rs = rs * (1.5f - 0.5f * z * rs * rs);   // Newton refine
        float o[8];
        #pragma unroll
        for (int j = 0; j < 4; j++) {
            o[2 * j]     = fmaxf((v[j].x - mu) * rs * s.g1s[cbase + 2 * j]     + s.be1s[cbase + 2 * j],     0.f);
            o[2 * j + 1] = fmaxf((v[j].y - mu) * rs * s.g1s[cbase + 2 * j + 1] + s.be1s[cbase + 2 * j + 1], 0.f);
        }
        *(float4*)&s.h1s[rbase + i][cbase]     = make_float4(o[0], o[1], o[2], o[3]);
        *(float4*)&s.h1s[rbase + i][cbase + 4] = make_float4(o[4], o[5], o[6], o[7]);
    }

    // ---- GEMM2: h2 = h1 @ W2, streaming W2 in KC-row chunks w/ register prefetch ----
    #pragma unroll
    for (int i = 0; i < RPW; i++)
        #pragma unroll
        for (int j = 0; j < 4; j++) acc[i][j] = 0ull;

    #pragma unroll 1
    for (int c = 0; c < NCHUNK; ++c) {
        __syncthreads();                 // W2s free (h1s visible on first iter too)
        float4* w2s4 = (float4*)&s.W2s[0][0];
        #pragma unroll
        for (int q = 0; q < 4; q++) w2s4[q * 256 + tid] = pre[q];
        if (c + 1 < NCHUNK) {
            const float4* w2g = (const float4*)W2;
            #pragma unroll
            for (int q = 0; q < 4; q++) pre[q] = w2g[(c + 1) * 1024 + q * 256 + tid];
        }
        __syncthreads();

        const int kb = c * KC;
        #pragma unroll
        for (int kk2 = 0; kk2 < KC / 2; ++kk2) {
            float2 av[RPW];
            #pragma unroll
            for (int i = 0; i < RPW; i++)
                av[i] = *(const float2*)&s.h1s[rbase + i][kb + 2 * kk2];
            #pragma unroll
            for (int t = 0; t < 2; ++t) {
                const int kk = 2 * kk2 + t;
                float4 w0 = *(const float4*)&s.W2s[kk][cbase];
                float4 w1 = *(const float4*)&s.W2s[kk][cbase + 4];
                ull wp0 = pack2(w0.x, w0.y), wp1 = pack2(w0.z, w0.w);
                ull wp2 = pack2(w1.x, w1.y), wp3 = pack2(w1.z, w1.w);
                #pragma unroll
                for (int i = 0; i < RPW; i++) {
                    float a = t ? av[i].y : av[i].x;
                    ull ap = pack2(a, a);
                    fma2(acc[i][0], ap, wp0);
                    fma2(acc[i][1], ap, wp1);
                    fma2(acc[i][2], ap, wp2);
                    fma2(acc[i][3], ap, wp3);
                }
            }
        }
    }

    // ---- bias + LayerNorm2 + ReLU + Linear(H->1), all in registers ----
    float rtot = 0.f;
    #pragma unroll
    for (int i = 0; i < RPW; i++) {
        float2 v[4];
        float sum = 0.f, sq = 0.f;
        #pragma unroll
        for (int j = 0; j < 4; j++) {
            v[j] = unpack2(acc[i][j]);
            v[j].x += s.b2s[cbase + 2 * j];
            v[j].y += s.b2s[cbase + 2 * j + 1];
            sum += v[j].x + v[j].y;
            sq = fmaf(v[j].x, v[j].x, sq);
            sq = fmaf(v[j].y, v[j].y, sq);
        }
        sum = warp_sum(sum);
        sq  = warp_sum(sq);
        float mu  = sum * (1.f / HID);
        float var = sq * (1.f / HID) - mu * mu;
        float z   = var + EPS;
        float rs  = rsqrtf(z);
        rs = rs * (1.5f - 0.5f * z * rs * rs);
        float rp = 0.f;
        #pragma unroll
        for (int j = 0; j < 4; j++) {
            float a = fmaxf((v[j].x - mu) * rs * s.g2s[cbase + 2 * j]     + s.be2s[cbase + 2 * j],     0.f);
            float b = fmaxf((v[j].y - mu) * rs * s.g2s[cbase + 2 * j + 1] + s.be2s[cbase + 2 * j + 1], 0.f);
            rp = fmaf(a, s.W3s[cbase + 2 * j],     rp);
            rp = fmaf(b, s.W3s[cbase + 2 * j + 1], rp);
        }
        rtot += rp;
    }
    rtot = warp_sum(rtot);
    if (lane == 0) s.bsum[warp] = rtot;
    __syncthreads();
    if (tid == 0) {
        float t = 0.f;
        #pragma unroll
        for (int w = 0; w < 8; w++) t += s.bsum[w];
        t += (float)ROWS * b3[0];          // +b3 per row
        g_partials[blockIdx.x] = t;
    }
}

// Deterministic final reduction: out[b] = sum of NROWBLK per-block partials
__global__ void reduce_kernel(float* __restrict__ out)
{
    const int b = threadIdx.x;             // 256 threads, one batch each
    float t = 0.f;
    #pragma unroll
    for (int i = 0; i < NROWBLK; i++) t += g_partials[b * NROWBLK + i];
    out[b] = t;
}

extern "C" void kernel_launch(void* const* d_in, const int* in_sizes, int n_in,
                              void* d_out, int out_size)
{
    const float* obs = (const float*)d_in[0];
    const float* act = (const float*)d_in[1];
    const float* W1  = (const float*)d_in[2];
    const float* b1  = (const float*)d_in[3];
    const float* g1  = (const float*)d_in[4];
    const float* be1 = (const float*)d_in[5];
    const float* W2  = (const float*)d_in[6];
    const float* b2  = (const float*)d_in[7];
    const float* g2  = (const float*)d_in[8];
    const float* be2 = (const float*)d_in[9];
    const float* W3  = (const float*)d_in[10];
    const float* b3  = (const float*)d_in[11];

    cudaFuncSetAttribute(fused_mlp_kernel,
                         cudaFuncAttributeMaxDynamicSharedMemorySize,
                         (int)sizeof(Smem));

    fused_mlp_kernel<<<NBLOCKS, THREADS, sizeof(Smem)>>>(
        obs, act, W1, b1, g1, be1, W2, b2, g2, be2, W3, b3);

    reduce_kernel<<<1, BATCH>>>((float*)d_out);
}